// round 4
// baseline (speedup 1.0000x reference)
#include <cuda_runtime.h>
#include <cstdint>

// MazeBrain: recurrent adaptive-LIF, T=1200, B=16, N=1024.
// One CTA per batch. Ballot-layout bitmap exchange, atomic list build by warp 0,
// 4-wide batched sparse gather, 2-step-deep DRAM prefetch.

#define T_STEPS 1200
#define BATCH   16
#define NN      1024
#define WHIST   1000
#define TPB     256     // thread owns neurons 4*tid .. 4*tid+3

__global__ void __launch_bounds__(TPB, 1)
mazebrain_kernel(const float* __restrict__ Iext,   // [T,B,N]
                 const float* __restrict__ W,      // [N,N]
                 float* __restrict__ out)          // [2,T,B,N]: spikes, potentials
{
    const int b    = blockIdx.x;
    const int tid  = threadIdx.x;
    const int lane = tid & 31;
    const int wid  = tid >> 5;
    const int m0   = tid * 4;

    __shared__ uint32_t words[2][32];   // spike bitmap, ballot layout, double-buffered
    __shared__ int      s_list[NN];     // dense spike list
    __shared__ int      s_cnt;          // atomic allocator (warp 0 only)
    __shared__ int      s_tot;          // snapshot for consumers

    if (tid < 32) words[0][tid] = 0;    // step -1: no spikes
    if (tid == 0) { s_cnt = 0; s_tot = 0; }
    __syncthreads();

    float v[4], adapt[4], thr[4], rsum[4];
    int   refr[4];
#pragma unroll
    for (int k = 0; k < 4; k++) {
        v[k] = -65.0f; adapt[k] = 0.0f; thr[k] = -55.0f; rsum[k] = 0.0f; refr[k] = 0;
    }

    float* __restrict__ spikes_out = out;
    float* __restrict__ pot_out    = out + (size_t)T_STEPS * BATCH * NN;
    const size_t stride = (size_t)BATCH * NN;
    const float* __restrict__ Wm = W + m0;

    size_t ob = (size_t)b * NN + m0;

    // 2-deep prefetch buffers (slot = t & 1)
    float4 IeB[2], hB[2];
    IeB[0] = __ldg((const float4*)(Iext + ob));
    IeB[1] = __ldg((const float4*)(Iext + ob + stride));
    hB[0] = make_float4(0.f, 0.f, 0.f, 0.f);
    hB[1] = make_float4(0.f, 0.f, 0.f, 0.f);

    int cur = 0;
    for (int t = 0; t < T_STEPS; t++) {
        const int pb = t & 1;
        const float4 Ie   = IeB[pb];
        const float4 hist = hB[pb];

        // ---- warp 0: bitmap -> dense list (atomic base alloc; order-free fp sum)
        if (wid == 0) {
            uint32_t w = words[cur][lane];
            int c = __popc(w);
            int base = 0;
            if (c) base = atomicAdd(&s_cnt, c);
            // ballot layout: word q, bit p  ->  neuron 128*(q>>2) + 4*p + (q&3)
            const int jb = ((lane >> 2) << 7) | (lane & 3);
            while (w) {
                int p = __ffs(w) - 1;
                w &= w - 1;
                s_list[base++] = jb + (p << 2);
            }
            __syncwarp();
            if (lane == 0) { s_tot = s_cnt; s_cnt = 0; }
        }
        __syncthreads();                 // list + s_tot visible

        // ---- sparse gather: I += sum over spiking j of W[j, m0..m0+3]
        const int tot = s_tot;
        float a0 = Ie.x, a1 = Ie.y, a2 = Ie.z, a3 = Ie.w;
        int s = 0;
        for (; s + 4 <= tot; s += 4) {
            int j0 = s_list[s], j1 = s_list[s + 1];
            int j2 = s_list[s + 2], j3 = s_list[s + 3];
            float4 w0 = *(const float4*)(Wm + ((size_t)j0 << 10));
            float4 w1 = *(const float4*)(Wm + ((size_t)j1 << 10));
            float4 w2 = *(const float4*)(Wm + ((size_t)j2 << 10));
            float4 w3 = *(const float4*)(Wm + ((size_t)j3 << 10));
            a0 += (w0.x + w1.x) + (w2.x + w3.x);
            a1 += (w0.y + w1.y) + (w2.y + w3.y);
            a2 += (w0.z + w1.z) + (w2.z + w3.z);
            a3 += (w0.w + w1.w) + (w2.w + w3.w);
        }
        for (; s < tot; s++) {
            float4 w4 = *(const float4*)(Wm + ((size_t)s_list[s] << 10));
            a0 += w4.x; a1 += w4.y; a2 += w4.z; a3 += w4.w;
        }
        float Iin[4] = {a0, a1, a2, a3};

        // ---- neuron update (integrate -> fire/reset -> adapt -> homeo)
        float spk[4], vout[4];
        bool  fired[4];
#pragma unroll
        for (int k = 0; k < 4; k++) {
            bool  active = (refr[k] <= 0);
            float v_int  = 0.9f * (v[k] + 65.0f) - 65.0f + Iin[k] - adapt[k];
            float v1     = active ? v_int : v[k];
            int   r1     = active ? refr[k] : (refr[k] - 1);
            fired[k] = (v1 >= thr[k]);
            spk[k]  = fired[k] ? 1.0f : 0.0f;
            v[k]    = fired[k] ? -70.0f : v1;
            vout[k] = v[k];
            adapt[k] = (fired[k] ? (adapt[k] + 0.2f) : adapt[k]) * 0.95f;
            refr[k]  = fired[k] ? 5 : r1;
        }

        // ---- exchange: 4 ballots per warp, lanes 0-3 store (ballot layout)
        const int nxt = cur ^ 1;
        uint32_t b0 = __ballot_sync(0xffffffffu, fired[0]);
        uint32_t b1 = __ballot_sync(0xffffffffu, fired[1]);
        uint32_t b2 = __ballot_sync(0xffffffffu, fired[2]);
        uint32_t b3 = __ballot_sync(0xffffffffu, fired[3]);
        if (lane < 4) {
            uint32_t mw = (lane == 0) ? b0 : (lane == 1) ? b1 : (lane == 2) ? b2 : b3;
            words[nxt][(wid << 2) | lane] = mw;
        }

        // ---- outputs (spikes region doubles as the homeostatic history ring)
        *(float4*)(spikes_out + ob) = make_float4(spk[0], spk[1], spk[2], spk[3]);
        *(float4*)(pot_out    + ob) = make_float4(vout[0], vout[1], vout[2], vout[3]);

        // ---- homeostatic sliding-window rate
        rsum[0] += spk[0] - hist.x; rsum[1] += spk[1] - hist.y;
        rsum[2] += spk[2] - hist.z; rsum[3] += spk[3] - hist.w;
        if (t + 1 >= WHIST) {
#pragma unroll
            for (int k = 0; k < 4; k++) {
                float ta = thr[k] + 0.001f * (rsum[k] * (1.0f / WHIST) - 0.01f);
                thr[k] = fminf(fmaxf(ta, 0.1f), 5.0f);
            }
        }

        // ---- prefetch step t+2 (2 steps of slack for DRAM latency)
        if (t + 2 < T_STEPS) {
            const size_t ob2 = ob + 2 * stride;
            IeB[pb] = __ldg((const float4*)(Iext + ob2));
            hB[pb]  = (t + 2 >= WHIST)
                    ? *(const float4*)(spikes_out + (ob2 - (size_t)WHIST * stride))
                    : make_float4(0.f, 0.f, 0.f, 0.f);
        }

        ob += stride;
        cur = nxt;
        __syncthreads();   // words[nxt] + s_cnt reset visible; list reads done
    }
}

extern "C" void kernel_launch(void* const* d_in, const int* in_sizes, int n_in,
                              void* d_out, int out_size)
{
    const float* input_current = (const float*)d_in[0];  // [T,B,N]
    const float* W_rec         = (const float*)d_in[1];  // [N,N]
    float* out                 = (float*)d_out;          // [2,T,B,N]
    (void)in_sizes; (void)n_in; (void)out_size;

    mazebrain_kernel<<<BATCH, TPB>>>(input_current, W_rec, out);
}

// round 5
// speedup vs baseline: 1.4553x; 1.4553x over previous
#include <cuda_runtime.h>
#include <cstdint>

// MazeBrain: recurrent adaptive-LIF, T=1200, B=16, N=1024.
// One CTA per batch. 512 threads, 2 columns/thread. Distributed atomic spike
// list (dual-parity monotonic counters + rings, ONE barrier per step).
// Gather runs 16 float2 loads in flight to cover L2 latency.

#define T_STEPS 1200
#define BATCH   16
#define NN      1024
#define WHIST   1000
#define TPB     512     // thread owns neurons 2*tid, 2*tid+1

__global__ void __launch_bounds__(TPB, 1)
mazebrain_kernel(const float* __restrict__ Iext,   // [T,B,N]
                 const float* __restrict__ W,      // [N,N]
                 float* __restrict__ out)          // [2,T,B,N]: spikes, potentials
{
    const int b   = blockIdx.x;
    const int tid = threadIdx.x;
    const int m0  = tid * 2;

    __shared__ int s_list[2][NN];   // per-parity spike ring
    __shared__ int s_cnt[2];        // per-parity monotonic counters

    if (tid == 0) { s_cnt[0] = 0; s_cnt[1] = 0; }
    __syncthreads();

    float v[2], adapt[2], thr[2], rsum[2];
    int   refr[2];
#pragma unroll
    for (int k = 0; k < 2; k++) {
        v[k] = -65.0f; adapt[k] = 0.0f; thr[k] = -55.0f; rsum[k] = 0.0f; refr[k] = 0;
    }
    int consumed[2] = {0, 0};       // per-parity: entries already gathered

    float* __restrict__ spikes_out = out;
    float* __restrict__ pot_out    = out + (size_t)T_STEPS * BATCH * NN;
    const size_t stride = (size_t)BATCH * NN;
    const float* __restrict__ Wm = W + m0;

    size_t ob = (size_t)b * NN + m0;
    float2 Ie_next   = __ldg((const float2*)(Iext + ob));
    float2 hist_next = make_float2(0.f, 0.f);

    for (int t = 0; t < T_STEPS; t++) {
        const int p = t & 1;        // append parity (this step's spikes)
        const int q = p ^ 1;        // consume parity (previous step's spikes)
        const float2 Ie   = Ie_next;
        const float2 hist = hist_next;

        // ---- sparse gather of previous step's spikes (ring of parity q)
        const int e     = s_cnt[q];
        int       i     = consumed[q];
        int       n     = e - i;
        consumed[q]     = e;
        const int* __restrict__ lst = s_list[q];

        float a0 = Ie.x, a1 = Ie.y;
        while (n >= 16) {
            int j[16];
#pragma unroll
            for (int k = 0; k < 16; k++) j[k] = lst[(i + k) & (NN - 1)];
            float2 r[16];
#pragma unroll
            for (int k = 0; k < 16; k++)
                r[k] = *(const float2*)(Wm + ((size_t)j[k] << 10));
#pragma unroll
            for (int k = 0; k < 16; k++) { a0 += r[k].x; a1 += r[k].y; }
            i += 16; n -= 16;
        }
        if (n >= 8) {
            int j[8];
#pragma unroll
            for (int k = 0; k < 8; k++) j[k] = lst[(i + k) & (NN - 1)];
            float2 r[8];
#pragma unroll
            for (int k = 0; k < 8; k++)
                r[k] = *(const float2*)(Wm + ((size_t)j[k] << 10));
#pragma unroll
            for (int k = 0; k < 8; k++) { a0 += r[k].x; a1 += r[k].y; }
            i += 8; n -= 8;
        }
        if (n >= 4) {
            int j[4];
#pragma unroll
            for (int k = 0; k < 4; k++) j[k] = lst[(i + k) & (NN - 1)];
            float2 r[4];
#pragma unroll
            for (int k = 0; k < 4; k++)
                r[k] = *(const float2*)(Wm + ((size_t)j[k] << 10));
#pragma unroll
            for (int k = 0; k < 4; k++) { a0 += r[k].x; a1 += r[k].y; }
            i += 4; n -= 4;
        }
        while (n > 0) {
            float2 r = *(const float2*)(Wm + ((size_t)lst[i & (NN - 1)] << 10));
            a0 += r.x; a1 += r.y;
            i++; n--;
        }
        float Iin[2] = {a0, a1};

        // ---- neuron update (integrate -> fire/reset -> adapt -> homeo)
        float spk[2], vout[2];
        bool  fired[2];
#pragma unroll
        for (int k = 0; k < 2; k++) {
            bool  active = (refr[k] <= 0);
            float v_int  = 0.9f * (v[k] + 65.0f) - 65.0f + Iin[k] - adapt[k];
            float v1     = active ? v_int : v[k];
            int   r1     = active ? refr[k] : (refr[k] - 1);
            fired[k] = (v1 >= thr[k]);
            spk[k]  = fired[k] ? 1.0f : 0.0f;
            v[k]    = fired[k] ? -70.0f : v1;
            vout[k] = v[k];
            adapt[k] = (fired[k] ? (adapt[k] + 0.2f) : adapt[k]) * 0.95f;
            refr[k]  = fired[k] ? 5 : r1;
        }

        // ---- distributed append of this step's spikes (parity p ring)
#pragma unroll
        for (int k = 0; k < 2; k++) {
            if (fired[k]) {
                int idx = atomicAdd(&s_cnt[p], 1);
                s_list[p][idx & (NN - 1)] = m0 + k;
            }
        }

        // ---- outputs (spikes region doubles as the homeostatic history ring)
        *(float2*)(spikes_out + ob) = make_float2(spk[0], spk[1]);
        *(float2*)(pot_out    + ob) = make_float2(vout[0], vout[1]);

        // ---- homeostatic sliding-window rate
        rsum[0] += spk[0] - hist.x;
        rsum[1] += spk[1] - hist.y;
        if (t + 1 >= WHIST) {
#pragma unroll
            for (int k = 0; k < 2; k++) {
                float ta = thr[k] + 0.001f * (rsum[k] * (1.0f / WHIST) - 0.01f);
                thr[k] = fminf(fmaxf(ta, 0.1f), 5.0f);
            }
        }

        // ---- prefetch next step's inputs
        const size_t ob_next = ob + stride;
        if (t + 1 < T_STEPS) {
            Ie_next = __ldg((const float2*)(Iext + ob_next));
            hist_next = (t + 1 >= WHIST)
                      ? *(const float2*)(spikes_out + (ob_next - (size_t)WHIST * stride))
                      : make_float2(0.f, 0.f);
        }
        ob = ob_next;

        __syncthreads();   // orders append(t) before gather(t+1); counters stable
    }
}

extern "C" void kernel_launch(void* const* d_in, const int* in_sizes, int n_in,
                              void* d_out, int out_size)
{
    const float* input_current = (const float*)d_in[0];  // [T,B,N]
    const float* W_rec         = (const float*)d_in[1];  // [N,N]
    float* out                 = (float*)d_out;          // [2,T,B,N]
    (void)in_sizes; (void)n_in; (void)out_size;

    mazebrain_kernel<<<BATCH, TPB>>>(input_current, W_rec, out);
}